// round 8
// baseline (speedup 1.0000x reference)
#include <cuda_runtime.h>
#include <cuda_bf16.h>

#define NB   4
#define LF   256
#define LS   128
#define NC   8
#define NN   512
#define PL   (NC*LF*NN)      // 1,048,576 plane size (one float4 per (c,t,n))
#define TOT  (NC*LF*NN*16)

// scratch: meta = {dt, sc, zg, e1} per (di-plane, c,t,n); B/C per (q-plane, c,t,n)
__device__ __align__(16) float4 g_meta4[16*PL];
__device__ __align__(16) float4 g_B4[4*PL];
__device__ __align__(16) float4 g_C4[4*PL];
__device__ __align__(16) float  g_yf[TOT];
__device__ __align__(16) float  g_part[NC*16*NN*8];

__device__ __forceinline__ float fsig(float x) {
    float e = __expf(-fabsf(x));
    float r = __frcp_rn(1.0f + e);
    return (x >= 0.0f) ? r : e * r;
}
__device__ __forceinline__ float fsilu(float x) { return x * fsig(x); }
__device__ __forceinline__ float dot16s(const float* sc, const float* w) {
    float r = sc[0] * w[0];
    #pragma unroll
    for (int i = 1; i < 16; ++i) r = fmaf(sc[i], w[i], r);
    return r;
}

// ========== Kernel A: folded lift+in_proj + conv + silu + x_proj + dt + exp(-dt) ==========
// grid (t=256, c=8), block 256 threads = n-half; all scratch stores coalesced (plane-major)
__global__ void __launch_bounds__(256) kA(
    const float* __restrict__ x,     const float* __restrict__ lift_w,
    const float* __restrict__ lift_b,const float* __restrict__ ipw,
    const float* __restrict__ conv_w,const float* __restrict__ conv_b,
    const float* __restrict__ xpw,   const float* __restrict__ dt_w,
    const float* __restrict__ dt_b)
{
    __shared__ float s_xpw[528];
    __shared__ float s_w1[32], s_b1[32], s_cw[64], s_cb[16], s_dtw[16], s_dtb[16];

    const int tid = threadIdx.x, t = blockIdx.x, c = blockIdx.y;

    for (int i = tid; i < 528; i += 256) s_xpw[i] = xpw[c*528 + i];
    if (tid < 32) {
        float w = 0.f, bs = 0.f;
        #pragma unroll
        for (int d = 0; d < 8; ++d) {
            float ip = ipw[(c*32 + tid)*8 + d];
            w  = fmaf(lift_w[c*8 + d], ip, w);
            bs = fmaf(lift_b[c*8 + d], ip, bs);
        }
        s_w1[tid] = w; s_b1[tid] = bs;
    } else if (tid < 96)  s_cw [tid-32]  = conv_w[c*64 + (tid-32)];
    else if (tid < 112)   s_cb [tid-96]  = conv_b[c*16 + (tid-96)];
    else if (tid < 128)   s_dtw[tid-112] = dt_w  [c*16 + (tid-112)];
    else if (tid < 144)   s_dtb[tid-128] = dt_b  [c*16 + (tid-128)];
    __syncthreads();

    const float m0 = (t >= 3) ? 1.f : 0.f;
    const float m1 = (t >= 2) ? 1.f : 0.f;
    const float m2 = (t >= 1) ? 1.f : 0.f;

    #pragma unroll
    for (int half = 0; half < 2; ++half) {
        const int n = tid + half*256;
        const int b = n >> 7, ls = n & 127;
        const float* xb = x + ((size_t)b*LF*LS + ls)*NC + c;
        const float xv0 = (t >= 3) ? __ldg(xb + (size_t)(t-3)*(LS*NC)) : 0.f;
        const float xv1 = (t >= 2) ? __ldg(xb + (size_t)(t-2)*(LS*NC)) : 0.f;
        const float xv2 = (t >= 1) ? __ldg(xb + (size_t)(t-1)*(LS*NC)) : 0.f;
        const float xv3 =            __ldg(xb + (size_t)t*(LS*NC));

        float sc[16];
        #pragma unroll
        for (int di = 0; di < 16; ++di) {
            float w = s_w1[di], bs = s_b1[di];
            float acc = s_cb[di];
            acc = fmaf(m0 * fmaf(xv0, w, bs), s_cw[di*4+0], acc);
            acc = fmaf(m1 * fmaf(xv1, w, bs), s_cw[di*4+1], acc);
            acc = fmaf(m2 * fmaf(xv2, w, bs), s_cw[di*4+2], acc);
            acc = fmaf(     fmaf(xv3, w, bs), s_cw[di*4+3], acc);
            sc[di] = fsilu(acc);
        }

        const int ctn = (c*LF + t)*NN + n;
        const float dtlo = dot16s(sc, s_xpw);

        // meta planes: {dt, sc, zg, e1 = exp(-dt) = sigmoid(-v)}
        #pragma unroll
        for (int di = 0; di < 16; ++di) {
            float v  = fmaf(dtlo, s_dtw[di], s_dtb[di]);
            float e  = __expf(-fabsf(v));
            float r  = __frcp_rn(1.0f + e);
            float dt = fmaxf(v, 0.0f) + __logf(1.0f + e);   // softplus(v)
            float e1 = (v >= 0.0f) ? e * r : r;             // sigmoid(-v) = exp(-dt)
            float zg = fsilu(fmaf(xv3, s_w1[16+di], s_b1[16+di]));
            g_meta4[di*PL + ctn] = make_float4(dt, sc[di], zg, e1);
        }
        // B, C planes
        #pragma unroll
        for (int q = 0; q < 4; ++q) {
            float v0 = dot16s(sc, s_xpw + (1 + 4*q + 0)*16);
            float v1 = dot16s(sc, s_xpw + (1 + 4*q + 1)*16);
            float v2 = dot16s(sc, s_xpw + (1 + 4*q + 2)*16);
            float v3 = dot16s(sc, s_xpw + (1 + 4*q + 3)*16);
            g_B4[q*PL + ctn] = make_float4(v0, v1, v2, v3);
        }
        #pragma unroll
        for (int q = 0; q < 4; ++q) {
            float v0 = dot16s(sc, s_xpw + (17 + 4*q + 0)*16);
            float v1 = dot16s(sc, s_xpw + (17 + 4*q + 1)*16);
            float v2 = dot16s(sc, s_xpw + (17 + 4*q + 2)*16);
            float v3 = dot16s(sc, s_xpw + (17 + 4*q + 3)*16);
            g_C4[q*PL + ctn] = make_float4(v0, v1, v2, v3);
        }
    }
}

// ========== Kernel B: selective scan, thread = (c,n,di,sq), NO transcendentals ==========
__global__ void __launch_bounds__(256) kB(
    const float* __restrict__ A_log, const float* __restrict__ D_skip)
{
    const int id = blockIdx.x*256 + threadIdx.x;
    const int sq = id & 3;
    const int di = (id >> 2) & 15;
    const int n  = (id >> 6) & 511;
    const int c  = id >> 15;

    // verify A_log structure: A[s] = -(s+1)  (then dA[s] = e1^(s+1), e1 = exp(-dt))
    float A[4];
    bool st = true;
    #pragma unroll
    for (int r = 0; r < 4; ++r) {
        A[r] = -__expf(__ldg(&A_log[(c*16 + di)*16 + 4*sq + r]));
        float tgt = -(float)(4*sq + r + 1);
        st = st && (fabsf(A[r] - tgt) <= 1e-4f * (4*sq + r + 1));
    }
    st = __all_sync(0xffffffffu, st);
    const float Dsk = __ldg(&D_skip[c*16 + di]);

    float h0 = 0.f, h1 = 0.f, h2 = 0.f, h3 = 0.f;
    const int ctn0 = c*LF*NN + n;
    const float4* MP = g_meta4 + di*PL;
    const float4* BP = g_B4 + sq*PL;
    const float4* CP = g_C4 + sq*PL;

    if (st) {
        #pragma unroll 4
        for (int t = 0; t < LF; ++t) {
            const int ctn = ctn0 + t*NN;
            float4 m  = __ldg(&MP[ctn]);   // {dt, sc, zg, e1}
            float4 Bq = __ldg(&BP[ctn]);
            float4 Cq = __ldg(&CP[ctn]);
            float e1 = m.w;
            float e2 = e1*e1, e3 = e2*e1, e4 = e2*e2;
            float e8 = e4*e4;
            float base = (sq == 0) ? 1.f : (sq == 1) ? e4 : (sq == 2) ? e8 : e8*e4;
            float u = m.x * m.y;
            h0 = fmaf(base*e1, h0, u*Bq.x);
            h1 = fmaf(base*e2, h1, u*Bq.y);
            h2 = fmaf(base*e3, h2, u*Bq.z);
            h3 = fmaf(base*e4, h3, u*Bq.w);
            float y = h0*Cq.x;
            y = fmaf(h1, Cq.y, y); y = fmaf(h2, Cq.z, y); y = fmaf(h3, Cq.w, y);
            y += __shfl_xor_sync(0xffffffffu, y, 1);
            y += __shfl_xor_sync(0xffffffffu, y, 2);
            if (sq == 0) g_yf[ctn*16 + di] = fmaf(Dsk, m.y, y) * m.z;
        }
    } else {
        #pragma unroll 2
        for (int t = 0; t < LF; ++t) {
            const int ctn = ctn0 + t*NN;
            float4 m  = __ldg(&MP[ctn]);
            float4 Bq = __ldg(&BP[ctn]);
            float4 Cq = __ldg(&CP[ctn]);
            float u = m.x * m.y;
            h0 = fmaf(__expf(m.x*A[0]), h0, u*Bq.x);
            h1 = fmaf(__expf(m.x*A[1]), h1, u*Bq.y);
            h2 = fmaf(__expf(m.x*A[2]), h2, u*Bq.z);
            h3 = fmaf(__expf(m.x*A[3]), h3, u*Bq.w);
            float y = h0*Cq.x;
            y = fmaf(h1, Cq.y, y); y = fmaf(h2, Cq.z, y); y = fmaf(h3, Cq.w, y);
            y += __shfl_xor_sync(0xffffffffu, y, 1);
            y += __shfl_xor_sync(0xffffffffu, y, 2);
            if (sq == 0) g_yf[ctn*16 + di] = fmaf(Dsk, m.y, y) * m.z;
        }
    }
}

// ========== Kernel C: folded out_proj∘blk + partial time-pooling ==========
__global__ void __launch_bounds__(256) kC(
    const float* __restrict__ out_w, const float* __restrict__ blk_w,
    const float* __restrict__ blk_b)
{
    const int id = blockIdx.x*256 + threadIdx.x;
    const int n = id & 511, chunk = (id >> 9) & 15, c = id >> 13;
    const int tid = threadIdx.x;

    __shared__ float s_M[8][16];
    __shared__ float s_bb[8];
    if (tid < 128) {
        int d = tid >> 4, i = tid & 15;
        float m = 0.f;
        #pragma unroll
        for (int e = 0; e < 8; ++e)
            m = fmaf(blk_w[(c*8+d)*8+e], out_w[(c*8+e)*16+i], m);
        s_M[d][i] = m;
        if (i == 0) s_bb[d] = blk_b[c*8+d];
    }
    __syncthreads();

    float acc[8] = {0,0,0,0,0,0,0,0};
    const float4* Y4 = reinterpret_cast<const float4*>(g_yf);
    #pragma unroll 2
    for (int tt = 0; tt < 16; ++tt) {
        int t = chunk*16 + tt;
        int o = ((c*LF + t)*NN + n)*16;
        float4 a = __ldg(&Y4[(o>>2)+0]), b = __ldg(&Y4[(o>>2)+1]);
        float4 cc = __ldg(&Y4[(o>>2)+2]), dd = __ldg(&Y4[(o>>2)+3]);
        float y[16] = {a.x,a.y,a.z,a.w, b.x,b.y,b.z,b.w,
                       cc.x,cc.y,cc.z,cc.w, dd.x,dd.y,dd.z,dd.w};
        #pragma unroll
        for (int d = 0; d < 8; ++d) {
            float v = s_bb[d];
            #pragma unroll
            for (int i = 0; i < 16; ++i) v = fmaf(y[i], s_M[d][i], v);
            acc[d] += fsilu(v);
        }
    }
    #pragma unroll
    for (int d = 0; d < 8; ++d)
        g_part[((c*16 + chunk)*NN + n)*8 + d] = acc[d];
}

// ========== Kernel D: final pooling + LayerNorm(64) ==========
__global__ void __launch_bounds__(64) kD(
    const float* __restrict__ ln_g, const float* __restrict__ ln_b,
    float* __restrict__ out)
{
    const int n = blockIdx.x, f = threadIdx.x;
    const int c = f >> 3, d = f & 7;
    float s = 0.f;
    #pragma unroll
    for (int ch = 0; ch < 16; ++ch)
        s += g_part[((c*16 + ch)*NN + n)*8 + d];
    float feat = s * (1.0f/256.0f);

    __shared__ float buf[64];
    buf[f] = feat;
    __syncthreads();
    float s1 = 0.f, s2 = 0.f;
    #pragma unroll
    for (int i = 0; i < 64; ++i) { float v = buf[i]; s1 += v; s2 = fmaf(v, v, s2); }
    float mu  = s1 * (1.0f/64.0f);
    float var = fmaxf(s2 * (1.0f/64.0f) - mu*mu, 0.f);
    float inv = rsqrtf(var + 1e-5f);
    out[n*64 + f] = (feat - mu) * inv * ln_g[f] + ln_b[f];
}

extern "C" void kernel_launch(void* const* d_in, const int* in_sizes, int n_in,
                              void* d_out, int out_size) {
    const float* x      = (const float*)d_in[0];
    const float* lift_w = (const float*)d_in[1];
    const float* lift_b = (const float*)d_in[2];
    const float* ipw    = (const float*)d_in[3];
    const float* conv_w = (const float*)d_in[4];
    const float* conv_b = (const float*)d_in[5];
    const float* xpw    = (const float*)d_in[6];
    const float* dt_w   = (const float*)d_in[7];
    const float* dt_b   = (const float*)d_in[8];
    const float* A_log  = (const float*)d_in[9];
    const float* D_skip = (const float*)d_in[10];
    const float* out_w  = (const float*)d_in[11];
    const float* blk_w  = (const float*)d_in[12];
    const float* blk_b  = (const float*)d_in[13];
    const float* ln_g   = (const float*)d_in[14];
    const float* ln_b   = (const float*)d_in[15];
    float* out = (float*)d_out;

    kA<<<dim3(LF, NC), 256>>>(x, lift_w, lift_b, ipw, conv_w, conv_b, xpw, dt_w, dt_b);
    kB<<<1024, 256>>>(A_log, D_skip);
    kC<<<256, 256>>>(out_w, blk_w, blk_b);
    kD<<<NN, 64>>>(ln_g, ln_b, out);
}

// round 12
// speedup vs baseline: 1.5053x; 1.5053x over previous
#include <cuda_runtime.h>
#include <cuda_bf16.h>

#define LF   256
#define LS   128
#define NC   8
#define NN   512
#define PL   (NC*LF*NN)      // 1,048,576  (c,t,n) sites

// scratch (plane-major; kB warp lanes = consecutive n => all coalesced)
__device__ __align__(16) float  g_scp[16*PL];   // sc per di-plane
__device__ __align__(16) float2 g_misc[PL];     // {dtlo, xv3}
__device__ __align__(16) float4 g_B4[4*PL];     // B quads per q-plane
__device__ __align__(16) float4 g_C4[4*PL];     // C quads per q-plane
__device__ __align__(16) float  g_yf[16*PL];    // gated y per di-plane
__device__ __align__(16) float  g_part[NC*16*NN*8];

__device__ __forceinline__ float fsig(float x) {
    float e = __expf(-fabsf(x));
    float r = __frcp_rn(1.0f + e);
    return (x >= 0.0f) ? r : e * r;
}
__device__ __forceinline__ float fsilu(float x) { return x * fsig(x); }
__device__ __forceinline__ float dot16s(const float* sc, const float* w) {
    float r = sc[0] * w[0];
    #pragma unroll
    for (int i = 1; i < 16; ++i) r = fmaf(sc[i], w[i], r);
    return r;
}

// ========== Kernel A: folded lift+in_proj + conv + silu + x_proj ==========
// grid (t=256, c=8), block 256 threads = n (2 halves); coalesced plane stores
__global__ void __launch_bounds__(256) kA(
    const float* __restrict__ x,     const float* __restrict__ lift_w,
    const float* __restrict__ lift_b,const float* __restrict__ ipw,
    const float* __restrict__ conv_w,const float* __restrict__ conv_b,
    const float* __restrict__ xpw)
{
    __shared__ float s_xpw[528];
    __shared__ float s_w1[16], s_b1[16], s_cw[64], s_cb[16];

    const int tid = threadIdx.x, t = blockIdx.x, c = blockIdx.y;

    for (int i = tid; i < 528; i += 256) s_xpw[i] = xpw[c*528 + i];
    if (tid < 16) {
        float w = 0.f, bs = 0.f;
        #pragma unroll
        for (int d = 0; d < 8; ++d) {
            float ip = ipw[(c*32 + tid)*8 + d];
            w  = fmaf(lift_w[c*8 + d], ip, w);
            bs = fmaf(lift_b[c*8 + d], ip, bs);
        }
        s_w1[tid] = w; s_b1[tid] = bs;
    } else if (tid < 80) s_cw[tid-16] = conv_w[c*64 + (tid-16)];
    else if (tid < 96)   s_cb[tid-80] = conv_b[c*16 + (tid-80)];
    __syncthreads();

    const float m0 = (t >= 3) ? 1.f : 0.f;
    const float m1 = (t >= 2) ? 1.f : 0.f;
    const float m2 = (t >= 1) ? 1.f : 0.f;

    #pragma unroll
    for (int half = 0; half < 2; ++half) {
        const int n = tid + half*256;
        const int b = n >> 7, ls = n & 127;
        const float* xb = x + ((size_t)b*LF*LS + ls)*NC + c;
        const float xv0 = (t >= 3) ? __ldg(xb + (size_t)(t-3)*(LS*NC)) : 0.f;
        const float xv1 = (t >= 2) ? __ldg(xb + (size_t)(t-2)*(LS*NC)) : 0.f;
        const float xv2 = (t >= 1) ? __ldg(xb + (size_t)(t-1)*(LS*NC)) : 0.f;
        const float xv3 =            __ldg(xb + (size_t)t*(LS*NC));

        float sc[16];
        #pragma unroll
        for (int di = 0; di < 16; ++di) {
            float w = s_w1[di], bs = s_b1[di];
            float acc = s_cb[di];
            acc = fmaf(m0 * fmaf(xv0, w, bs), s_cw[di*4+0], acc);
            acc = fmaf(m1 * fmaf(xv1, w, bs), s_cw[di*4+1], acc);
            acc = fmaf(m2 * fmaf(xv2, w, bs), s_cw[di*4+2], acc);
            acc = fmaf(     fmaf(xv3, w, bs), s_cw[di*4+3], acc);
            sc[di] = fsilu(acc);
        }

        const int ctn = (c*LF + t)*NN + n;
        #pragma unroll
        for (int di = 0; di < 16; ++di) g_scp[di*PL + ctn] = sc[di];

        const float dtlo = dot16s(sc, s_xpw);
        g_misc[ctn] = make_float2(dtlo, xv3);

        #pragma unroll
        for (int q = 0; q < 4; ++q) {
            float v0 = dot16s(sc, s_xpw + (1 + 4*q + 0)*16);
            float v1 = dot16s(sc, s_xpw + (1 + 4*q + 1)*16);
            float v2 = dot16s(sc, s_xpw + (1 + 4*q + 2)*16);
            float v3 = dot16s(sc, s_xpw + (1 + 4*q + 3)*16);
            g_B4[q*PL + ctn] = make_float4(v0, v1, v2, v3);
        }
        #pragma unroll
        for (int q = 0; q < 4; ++q) {
            float v0 = dot16s(sc, s_xpw + (17 + 4*q + 0)*16);
            float v1 = dot16s(sc, s_xpw + (17 + 4*q + 1)*16);
            float v2 = dot16s(sc, s_xpw + (17 + 4*q + 2)*16);
            float v3 = dot16s(sc, s_xpw + (17 + 4*q + 3)*16);
            g_C4[q*PL + ctn] = make_float4(v0, v1, v2, v3);
        }
    }
}

// ========== Kernel B: scan; thread = (c, di, n) holds h[16]; lanes = n ==========
__global__ void __launch_bounds__(256) kB(
    const float* __restrict__ A_log,  const float* __restrict__ D_skip,
    const float* __restrict__ dt_w,   const float* __restrict__ dt_b,
    const float* __restrict__ lift_w, const float* __restrict__ lift_b,
    const float* __restrict__ ipw)
{
    const int lane = threadIdx.x & 31;
    const int gw   = blockIdx.x*8 + (threadIdx.x >> 5);  // global warp id
    const int di   = gw & 15;
    const int nt   = (gw >> 4) & 15;
    const int c    = gw >> 8;
    const int n    = nt*32 + lane;

    // per-thread constants
    const float dtw = __ldg(&dt_w[c*16 + di]);
    const float dtb = __ldg(&dt_b[c*16 + di]);
    const float Dsk = __ldg(&D_skip[c*16 + di]);
    float w1z = 0.f, b1z = 0.f;
    #pragma unroll
    for (int d = 0; d < 8; ++d) {
        float ip = __ldg(&ipw[(c*32 + 16 + di)*8 + d]);
        w1z = fmaf(__ldg(&lift_w[c*8 + d]), ip, w1z);
        b1z = fmaf(__ldg(&lift_b[c*8 + d]), ip, b1z);
    }
    float A[16];
    bool st = true;
    #pragma unroll
    for (int s = 0; s < 16; ++s) {
        A[s] = -__expf(__ldg(&A_log[(c*16 + di)*16 + s]));
        st = st && (fabsf(A[s] + (float)(s+1)) <= 1e-4f * (float)(s+1));
    }
    st = __all_sync(0xffffffffu, st);

    float h[16];
    #pragma unroll
    for (int s = 0; s < 16; ++s) h[s] = 0.f;

    const int ctn0 = c*LF*NN + n;
    const float* SCP = g_scp + di*PL;
    float* YF = g_yf + di*PL;

    if (st) {
        #pragma unroll 2
        for (int t = 0; t < LF; ++t) {
            const int ctn = ctn0 + t*NN;
            float4 B0 = __ldg(&g_B4[0*PL + ctn]), B1 = __ldg(&g_B4[1*PL + ctn]);
            float4 B2 = __ldg(&g_B4[2*PL + ctn]), B3 = __ldg(&g_B4[3*PL + ctn]);
            float4 C0 = __ldg(&g_C4[0*PL + ctn]), C1 = __ldg(&g_C4[1*PL + ctn]);
            float4 C2 = __ldg(&g_C4[2*PL + ctn]), C3 = __ldg(&g_C4[3*PL + ctn]);
            float scv = __ldg(&SCP[ctn]);
            float2 ms = __ldg(&g_misc[ctn]);

            float v  = fmaf(ms.x, dtw, dtb);
            float e  = __expf(-fabsf(v));
            float r  = __frcp_rn(1.0f + e);
            float dt = fmaxf(v, 0.0f) + __logf(1.0f + e);   // softplus
            float e1 = (v >= 0.0f) ? e * r : r;             // exp(-dt)
            float gz = fmaf(ms.y, w1z, b1z);
            float zg = fsilu(gz);
            float u  = dt * scv;

            float p1 = e1,   p2 = p1*p1, p3 = p2*p1, p4 = p2*p2;
            float p5 = p4*p1, p6 = p4*p2, p7 = p4*p3, p8 = p4*p4;
            float p9 = p8*p1, p10= p8*p2, p11= p8*p3, p12= p8*p4;
            float p13= p8*p5, p14= p8*p6, p15= p8*p7, p16= p8*p8;

            h[0]  = fmaf(p1,  h[0],  u*B0.x);
            h[1]  = fmaf(p2,  h[1],  u*B0.y);
            h[2]  = fmaf(p3,  h[2],  u*B0.z);
            h[3]  = fmaf(p4,  h[3],  u*B0.w);
            h[4]  = fmaf(p5,  h[4],  u*B1.x);
            h[5]  = fmaf(p6,  h[5],  u*B1.y);
            h[6]  = fmaf(p7,  h[6],  u*B1.z);
            h[7]  = fmaf(p8,  h[7],  u*B1.w);
            h[8]  = fmaf(p9,  h[8],  u*B2.x);
            h[9]  = fmaf(p10, h[9],  u*B2.y);
            h[10] = fmaf(p11, h[10], u*B2.z);
            h[11] = fmaf(p12, h[11], u*B2.w);
            h[12] = fmaf(p13, h[12], u*B3.x);
            h[13] = fmaf(p14, h[13], u*B3.y);
            h[14] = fmaf(p15, h[14], u*B3.z);
            h[15] = fmaf(p16, h[15], u*B3.w);

            float y = h[0]*C0.x;
            y = fmaf(h[1],  C0.y, y); y = fmaf(h[2],  C0.z, y); y = fmaf(h[3],  C0.w, y);
            y = fmaf(h[4],  C1.x, y); y = fmaf(h[5],  C1.y, y); y = fmaf(h[6],  C1.z, y);
            y = fmaf(h[7],  C1.w, y); y = fmaf(h[8],  C2.x, y); y = fmaf(h[9],  C2.y, y);
            y = fmaf(h[10], C2.z, y); y = fmaf(h[11], C2.w, y); y = fmaf(h[12], C3.x, y);
            y = fmaf(h[13], C3.y, y); y = fmaf(h[14], C3.z, y); y = fmaf(h[15], C3.w, y);

            YF[ctn] = (y + Dsk*scv) * zg;
        }
    } else {
        #pragma unroll 1
        for (int t = 0; t < LF; ++t) {
            const int ctn = ctn0 + t*NN;
            float4 Bq[4], Cq[4];
            #pragma unroll
            for (int q = 0; q < 4; ++q) { Bq[q] = __ldg(&g_B4[q*PL + ctn]); Cq[q] = __ldg(&g_C4[q*PL + ctn]); }
            float scv = __ldg(&SCP[ctn]);
            float2 ms = __ldg(&g_misc[ctn]);

            float v  = fmaf(ms.x, dtw, dtb);
            float e  = __expf(-fabsf(v));
            float dt = fmaxf(v, 0.0f) + __logf(1.0f + e);
            float zg = fsilu(fmaf(ms.y, w1z, b1z));
            float u  = dt * scv;

            const float* Bs = (const float*)Bq;
            const float* Cs = (const float*)Cq;
            float y = 0.f;
            #pragma unroll
            for (int s = 0; s < 16; ++s) {
                h[s] = fmaf(__expf(dt*A[s]), h[s], u*Bs[s]);
                y = fmaf(h[s], Cs[s], y);
            }
            YF[ctn] = (y + Dsk*scv) * zg;
        }
    }
}

// ========== Kernel C: folded out_proj∘blk + partial time-pooling ==========
__global__ void __launch_bounds__(256) kC(
    const float* __restrict__ out_w, const float* __restrict__ blk_w,
    const float* __restrict__ blk_b)
{
    const int id = blockIdx.x*256 + threadIdx.x;
    const int n = id & 511, chunk = (id >> 9) & 15, c = id >> 13;
    const int tid = threadIdx.x;

    __shared__ float s_M[8][16];
    __shared__ float s_bb[8];
    if (tid < 128) {
        int d = tid >> 4, i = tid & 15;
        float m = 0.f;
        #pragma unroll
        for (int e = 0; e < 8; ++e)
            m = fmaf(blk_w[(c*8+d)*8+e], out_w[(c*8+e)*16+i], m);
        s_M[d][i] = m;
        if (i == 0) s_bb[d] = blk_b[c*8+d];
    }
    __syncthreads();

    float acc[8] = {0,0,0,0,0,0,0,0};
    #pragma unroll 2
    for (int tt = 0; tt < 16; ++tt) {
        const int ctn = (c*LF + chunk*16 + tt)*NN + n;
        float y[16];
        #pragma unroll
        for (int di = 0; di < 16; ++di) y[di] = __ldg(&g_yf[di*PL + ctn]);
        #pragma unroll
        for (int d = 0; d < 8; ++d) {
            float v = s_bb[d];
            #pragma unroll
            for (int i = 0; i < 16; ++i) v = fmaf(y[i], s_M[d][i], v);
            acc[d] += fsilu(v);
        }
    }
    #pragma unroll
    for (int d = 0; d < 8; ++d)
        g_part[((c*16 + chunk)*NN + n)*8 + d] = acc[d];
}

// ========== Kernel D: final pooling + LayerNorm(64) ==========
__global__ void __launch_bounds__(64) kD(
    const float* __restrict__ ln_g, const float* __restrict__ ln_b,
    float* __restrict__ out)
{
    const int n = blockIdx.x, f = threadIdx.x;
    const int c = f >> 3, d = f & 7;
    float s = 0.f;
    #pragma unroll
    for (int ch = 0; ch < 16; ++ch)
        s += g_part[((c*16 + ch)*NN + n)*8 + d];
    float feat = s * (1.0f/256.0f);

    __shared__ float buf[64];
    buf[f] = feat;
    __syncthreads();
    float s1 = 0.f, s2 = 0.f;
    #pragma unroll
    for (int i = 0; i < 64; ++i) { float v = buf[i]; s1 += v; s2 = fmaf(v, v, s2); }
    float mu  = s1 * (1.0f/64.0f);
    float var = fmaxf(s2 * (1.0f/64.0f) - mu*mu, 0.f);
    float inv = rsqrtf(var + 1e-5f);
    out[n*64 + f] = (feat - mu) * inv * ln_g[f] + ln_b[f];
}

extern "C" void kernel_launch(void* const* d_in, const int* in_sizes, int n_in,
                              void* d_out, int out_size) {
    const float* x      = (const float*)d_in[0];
    const float* lift_w = (const float*)d_in[1];
    const float* lift_b = (const float*)d_in[2];
    const float* ipw    = (const float*)d_in[3];
    const float* conv_w = (const float*)d_in[4];
    const float* conv_b = (const float*)d_in[5];
    const float* xpw    = (const float*)d_in[6];
    const float* dt_w   = (const float*)d_in[7];
    const float* dt_b   = (const float*)d_in[8];
    const float* A_log  = (const float*)d_in[9];
    const float* D_skip = (const float*)d_in[10];
    const float* out_w  = (const float*)d_in[11];
    const float* blk_w  = (const float*)d_in[12];
    const float* blk_b  = (const float*)d_in[13];
    const float* ln_g   = (const float*)d_in[14];
    const float* ln_b   = (const float*)d_in[15];
    float* out = (float*)d_out;

    kA<<<dim3(LF, NC), 256>>>(x, lift_w, lift_b, ipw, conv_w, conv_b, xpw);
    kB<<<256, 256>>>(A_log, D_skip, dt_w, dt_b, lift_w, lift_b, ipw);
    kC<<<256, 256>>>(out_w, blk_w, blk_b);
    kD<<<NN, 64>>>(ln_g, ln_b, out);
}

// round 13
// speedup vs baseline: 1.9493x; 1.2950x over previous
#include <cuda_runtime.h>
#include <cuda_bf16.h>

#define LF   256
#define LS   128
#define NC   8
#define NN   512
#define PL   (NC*LF*NN)      // 1,048,576  (c,t,n) sites

// scratch (plane-major; consumers' warp lanes = consecutive n => coalesced)
__device__ __align__(16) float  g_scp[16*PL];   // sc per di-plane
__device__ __align__(16) float2 g_misc[PL];     // {dtlo, xv3}
__device__ __align__(16) float4 g_B4[4*PL];     // B quads per q-plane
__device__ __align__(16) float4 g_C4[4*PL];     // C quads per q-plane
__device__ __align__(16) float  g_yf[16*PL];    // gated y per di-plane
__device__ __align__(16) float  g_part[NC*16*NN*8];

__device__ __forceinline__ float fsig(float x) {
    float e = __expf(-fabsf(x));
    float r = __frcp_rn(1.0f + e);
    return (x >= 0.0f) ? r : e * r;
}
__device__ __forceinline__ float fsilu(float x) { return x * fsig(x); }
__device__ __forceinline__ float dot16s(const float* sc, const float* w) {
    float r = sc[0] * w[0];
    #pragma unroll
    for (int i = 1; i < 16; ++i) r = fmaf(sc[i], w[i], r);
    return r;
}

// ========== Kernel A: folded lift+in_proj + conv + silu + x_proj ==========
__global__ void __launch_bounds__(256) kA(
    const float* __restrict__ x,     const float* __restrict__ lift_w,
    const float* __restrict__ lift_b,const float* __restrict__ ipw,
    const float* __restrict__ conv_w,const float* __restrict__ conv_b,
    const float* __restrict__ xpw)
{
    __shared__ float s_xpw[528];
    __shared__ float s_w1[16], s_b1[16], s_cw[64], s_cb[16];

    const int tid = threadIdx.x, t = blockIdx.x, c = blockIdx.y;

    for (int i = tid; i < 528; i += 256) s_xpw[i] = xpw[c*528 + i];
    if (tid < 16) {
        float w = 0.f, bs = 0.f;
        #pragma unroll
        for (int d = 0; d < 8; ++d) {
            float ip = ipw[(c*32 + tid)*8 + d];
            w  = fmaf(lift_w[c*8 + d], ip, w);
            bs = fmaf(lift_b[c*8 + d], ip, bs);
        }
        s_w1[tid] = w; s_b1[tid] = bs;
    } else if (tid < 80) s_cw[tid-16] = conv_w[c*64 + (tid-16)];
    else if (tid < 96)   s_cb[tid-80] = conv_b[c*16 + (tid-80)];
    __syncthreads();

    const float m0 = (t >= 3) ? 1.f : 0.f;
    const float m1 = (t >= 2) ? 1.f : 0.f;
    const float m2 = (t >= 1) ? 1.f : 0.f;

    #pragma unroll
    for (int half = 0; half < 2; ++half) {
        const int n = tid + half*256;
        const int b = n >> 7, ls = n & 127;
        const float* xb = x + ((size_t)b*LF*LS + ls)*NC + c;
        const float xv0 = (t >= 3) ? __ldg(xb + (size_t)(t-3)*(LS*NC)) : 0.f;
        const float xv1 = (t >= 2) ? __ldg(xb + (size_t)(t-2)*(LS*NC)) : 0.f;
        const float xv2 = (t >= 1) ? __ldg(xb + (size_t)(t-1)*(LS*NC)) : 0.f;
        const float xv3 =            __ldg(xb + (size_t)t*(LS*NC));

        float sc[16];
        #pragma unroll
        for (int di = 0; di < 16; ++di) {
            float w = s_w1[di], bs = s_b1[di];
            float acc = s_cb[di];
            acc = fmaf(m0 * fmaf(xv0, w, bs), s_cw[di*4+0], acc);
            acc = fmaf(m1 * fmaf(xv1, w, bs), s_cw[di*4+1], acc);
            acc = fmaf(m2 * fmaf(xv2, w, bs), s_cw[di*4+2], acc);
            acc = fmaf(     fmaf(xv3, w, bs), s_cw[di*4+3], acc);
            sc[di] = fsilu(acc);
        }

        const int ctn = (c*LF + t)*NN + n;
        #pragma unroll
        for (int di = 0; di < 16; ++di) g_scp[di*PL + ctn] = sc[di];

        const float dtlo = dot16s(sc, s_xpw);
        g_misc[ctn] = make_float2(dtlo, xv3);

        #pragma unroll
        for (int q = 0; q < 4; ++q) {
            float v0 = dot16s(sc, s_xpw + (1 + 4*q + 0)*16);
            float v1 = dot16s(sc, s_xpw + (1 + 4*q + 1)*16);
            float v2 = dot16s(sc, s_xpw + (1 + 4*q + 2)*16);
            float v3 = dot16s(sc, s_xpw + (1 + 4*q + 3)*16);
            g_B4[q*PL + ctn] = make_float4(v0, v1, v2, v3);
        }
        #pragma unroll
        for (int q = 0; q < 4; ++q) {
            float v0 = dot16s(sc, s_xpw + (17 + 4*q + 0)*16);
            float v1 = dot16s(sc, s_xpw + (17 + 4*q + 1)*16);
            float v2 = dot16s(sc, s_xpw + (17 + 4*q + 2)*16);
            float v3 = dot16s(sc, s_xpw + (17 + 4*q + 3)*16);
            g_C4[q*PL + ctn] = make_float4(v0, v1, v2, v3);
        }
    }
}

// ========== Kernel B: pipelined smem-staged scan ==========
// block = (c, 32-n tile); 8 warps, warp w owns di {2w, 2w+1}; lanes = n.
// Double-buffered cp.async staging of B/C/sc/misc; B/C loaded from global ONCE.
#define STG_BYTES 6400   // B 2048 | C 2048 | sc 2048 | misc 256

__device__ __forceinline__ void kb_stage(int site0, char* dst_base, int tid) {
    #pragma unroll
    for (int rep = 0; rep < 2; ++rep) {
        int idx = tid + rep*256;
        if (idx < 400) {
            unsigned dst = (unsigned)__cvta_generic_to_shared(dst_base) + idx*16;
            const void* src;
            if (idx < 128) {
                int q = idx >> 5, j = idx & 31;
                src = (const void*)&g_B4[q*PL + site0 + j];
            } else if (idx < 256) {
                int q = (idx >> 5) - 4, j = idx & 31;
                src = (const void*)&g_C4[q*PL + site0 + j];
            } else if (idx < 384) {
                int r = (idx - 256) >> 3, k = idx & 7;
                src = (const void*)((const char*)&g_scp[r*PL + site0] + k*16);
            } else {
                src = (const void*)((const char*)&g_misc[site0] + (idx - 384)*16);
            }
            asm volatile("cp.async.ca.shared.global [%0], [%1], 16;" :: "r"(dst), "l"(src));
        }
    }
    asm volatile("cp.async.commit_group;");
}

__global__ void __launch_bounds__(256, 1) kB(
    const float* __restrict__ A_log,  const float* __restrict__ D_skip,
    const float* __restrict__ dt_w,   const float* __restrict__ dt_b,
    const float* __restrict__ lift_w, const float* __restrict__ lift_b,
    const float* __restrict__ ipw)
{
    __shared__ __align__(16) char sbuf[2][STG_BYTES];

    const int tid  = threadIdx.x;
    const int w    = tid >> 5, lane = tid & 31;
    const int c    = blockIdx.x >> 4;
    const int n0   = (blockIdx.x & 15) * 32;
    const int di0  = 2*w, di1 = di0 + 1;
    const int base = (c*LF)*NN + n0;          // site at t=0

    // per-warp constants
    const float dtw0 = __ldg(&dt_w[c*16+di0]), dtw1 = __ldg(&dt_w[c*16+di1]);
    const float dtb0 = __ldg(&dt_b[c*16+di0]), dtb1 = __ldg(&dt_b[c*16+di1]);
    const float Dsk0 = __ldg(&D_skip[c*16+di0]), Dsk1 = __ldg(&D_skip[c*16+di1]);
    float w1z0 = 0.f, b1z0 = 0.f, w1z1 = 0.f, b1z1 = 0.f;
    #pragma unroll
    for (int d = 0; d < 8; ++d) {
        float lw = __ldg(&lift_w[c*8+d]), lb = __ldg(&lift_b[c*8+d]);
        float ip0 = __ldg(&ipw[(c*32 + 16 + di0)*8 + d]);
        float ip1 = __ldg(&ipw[(c*32 + 16 + di1)*8 + d]);
        w1z0 = fmaf(lw, ip0, w1z0); b1z0 = fmaf(lb, ip0, b1z0);
        w1z1 = fmaf(lw, ip1, w1z1); b1z1 = fmaf(lb, ip1, b1z1);
    }
    bool stl = true;
    #pragma unroll
    for (int s = 0; s < 16; ++s) {
        float a0 = -__expf(__ldg(&A_log[(c*16+di0)*16 + s]));
        float a1 = -__expf(__ldg(&A_log[(c*16+di1)*16 + s]));
        stl = stl && (fabsf(a0 + (float)(s+1)) <= 1e-4f*(s+1))
                  && (fabsf(a1 + (float)(s+1)) <= 1e-4f*(s+1));
    }
    const bool st = __all_sync(0xffffffffu, stl);

    float h0[16], h1[16];
    #pragma unroll
    for (int s = 0; s < 16; ++s) { h0[s] = 0.f; h1[s] = 0.f; }

    float* Y0 = g_yf + di0*PL + base + lane;
    float* Y1 = g_yf + di1*PL + base + lane;

    // prologue: stage t=0, t=1
    kb_stage(base + 0*NN, sbuf[0], tid);
    kb_stage(base + 1*NN, sbuf[1], tid);

    for (int t = 0; t < LF; ++t) {
        if (t < LF-1) { asm volatile("cp.async.wait_group 1;"); }
        else          { asm volatile("cp.async.wait_group 0;"); }
        __syncthreads();

        char* buf = sbuf[t & 1];
        const float4* sB = (const float4*)(buf);
        const float4* sC = (const float4*)(buf + 2048);
        const float*  sS = (const float* )(buf + 4096);
        const float2* sM = (const float2*)(buf + 6144);

        float4 B0 = sB[lane],    B1 = sB[32+lane], B2 = sB[64+lane], B3 = sB[96+lane];
        float4 C0 = sC[lane],    C1 = sC[32+lane], C2 = sC[64+lane], C3 = sC[96+lane];
        float  sc0 = sS[di0*32 + lane], sc1 = sS[di1*32 + lane];
        float2 ms  = sM[lane];

        // per-di dt / e1 / gate
        float v0 = fmaf(ms.x, dtw0, dtb0);
        float e0 = __expf(-fabsf(v0));
        float r0 = __frcp_rn(1.0f + e0);
        float dt0 = fmaxf(v0, 0.f) + __logf(1.0f + e0);
        float e1_0 = (v0 >= 0.f) ? e0*r0 : r0;
        float zg0 = fsilu(fmaf(ms.y, w1z0, b1z0));
        float u0  = dt0 * sc0;

        float v1 = fmaf(ms.x, dtw1, dtb1);
        float e1x = __expf(-fabsf(v1));
        float r1 = __frcp_rn(1.0f + e1x);
        float dt1 = fmaxf(v1, 0.f) + __logf(1.0f + e1x);
        float e1_1 = (v1 >= 0.f) ? e1x*r1 : r1;
        float zg1 = fsilu(fmaf(ms.y, w1z1, b1z1));
        float u1  = dt1 * sc1;

        float y0, y1;
        if (st) {
            // di0
            {
                float p1=e1_0, p2=p1*p1, p3=p2*p1, p4=p2*p2;
                float p5=p4*p1, p6=p4*p2, p7=p4*p3, p8=p4*p4;
                float p9=p8*p1, p10=p8*p2, p11=p8*p3, p12=p8*p4;
                float p13=p8*p5, p14=p8*p6, p15=p8*p7, p16=p8*p8;
                h0[0]=fmaf(p1,h0[0],u0*B0.x);   h0[1]=fmaf(p2,h0[1],u0*B0.y);
                h0[2]=fmaf(p3,h0[2],u0*B0.z);   h0[3]=fmaf(p4,h0[3],u0*B0.w);
                h0[4]=fmaf(p5,h0[4],u0*B1.x);   h0[5]=fmaf(p6,h0[5],u0*B1.y);
                h0[6]=fmaf(p7,h0[6],u0*B1.z);   h0[7]=fmaf(p8,h0[7],u0*B1.w);
                h0[8]=fmaf(p9,h0[8],u0*B2.x);   h0[9]=fmaf(p10,h0[9],u0*B2.y);
                h0[10]=fmaf(p11,h0[10],u0*B2.z);h0[11]=fmaf(p12,h0[11],u0*B2.w);
                h0[12]=fmaf(p13,h0[12],u0*B3.x);h0[13]=fmaf(p14,h0[13],u0*B3.y);
                h0[14]=fmaf(p15,h0[14],u0*B3.z);h0[15]=fmaf(p16,h0[15],u0*B3.w);
                y0 = h0[0]*C0.x;
                y0=fmaf(h0[1],C0.y,y0);  y0=fmaf(h0[2],C0.z,y0);  y0=fmaf(h0[3],C0.w,y0);
                y0=fmaf(h0[4],C1.x,y0);  y0=fmaf(h0[5],C1.y,y0);  y0=fmaf(h0[6],C1.z,y0);
                y0=fmaf(h0[7],C1.w,y0);  y0=fmaf(h0[8],C2.x,y0);  y0=fmaf(h0[9],C2.y,y0);
                y0=fmaf(h0[10],C2.z,y0); y0=fmaf(h0[11],C2.w,y0); y0=fmaf(h0[12],C3.x,y0);
                y0=fmaf(h0[13],C3.y,y0); y0=fmaf(h0[14],C3.z,y0); y0=fmaf(h0[15],C3.w,y0);
            }
            // di1
            {
                float p1=e1_1, p2=p1*p1, p3=p2*p1, p4=p2*p2;
                float p5=p4*p1, p6=p4*p2, p7=p4*p3, p8=p4*p4;
                float p9=p8*p1, p10=p8*p2, p11=p8*p3, p12=p8*p4;
                float p13=p8*p5, p14=p8*p6, p15=p8*p7, p16=p8*p8;
                h1[0]=fmaf(p1,h1[0],u1*B0.x);   h1[1]=fmaf(p2,h1[1],u1*B0.y);
                h1[2]=fmaf(p3,h1[2],u1*B0.z);   h1[3]=fmaf(p4,h1[3],u1*B0.w);
                h1[4]=fmaf(p5,h1[4],u1*B1.x);   h1[5]=fmaf(p6,h1[5],u1*B1.y);
                h1[6]=fmaf(p7,h1[6],u1*B1.z);   h1[7]=fmaf(p8,h1[7],u1*B1.w);
                h1[8]=fmaf(p9,h1[8],u1*B2.x);   h1[9]=fmaf(p10,h1[9],u1*B2.y);
                h1[10]=fmaf(p11,h1[10],u1*B2.z);h1[11]=fmaf(p12,h1[11],u1*B2.w);
                h1[12]=fmaf(p13,h1[12],u1*B3.x);h1[13]=fmaf(p14,h1[13],u1*B3.y);
                h1[14]=fmaf(p15,h1[14],u1*B3.z);h1[15]=fmaf(p16,h1[15],u1*B3.w);
                y1 = h1[0]*C0.x;
                y1=fmaf(h1[1],C0.y,y1);  y1=fmaf(h1[2],C0.z,y1);  y1=fmaf(h1[3],C0.w,y1);
                y1=fmaf(h1[4],C1.x,y1);  y1=fmaf(h1[5],C1.y,y1);  y1=fmaf(h1[6],C1.z,y1);
                y1=fmaf(h1[7],C1.w,y1);  y1=fmaf(h1[8],C2.x,y1);  y1=fmaf(h1[9],C2.y,y1);
                y1=fmaf(h1[10],C2.z,y1); y1=fmaf(h1[11],C2.w,y1); y1=fmaf(h1[12],C3.x,y1);
                y1=fmaf(h1[13],C3.y,y1); y1=fmaf(h1[14],C3.z,y1); y1=fmaf(h1[15],C3.w,y1);
            }
        } else {
            // generic A path (rare): recompute A from A_log each step
            const float* Bs = &B0.x;  // B0..B3,C0..C3 are contiguous locals
            float yy0 = 0.f, yy1 = 0.f;
            float Bv[16] = {B0.x,B0.y,B0.z,B0.w, B1.x,B1.y,B1.z,B1.w,
                            B2.x,B2.y,B2.z,B2.w, B3.x,B3.y,B3.z,B3.w};
            float Cv[16] = {C0.x,C0.y,C0.z,C0.w, C1.x,C1.y,C1.z,C1.w,
                            C2.x,C2.y,C2.z,C2.w, C3.x,C3.y,C3.z,C3.w};
            (void)Bs;
            #pragma unroll
            for (int s = 0; s < 16; ++s) {
                float a0 = -__expf(__ldg(&A_log[(c*16+di0)*16 + s]));
                float a1 = -__expf(__ldg(&A_log[(c*16+di1)*16 + s]));
                h0[s] = fmaf(__expf(dt0*a0), h0[s], u0*Bv[s]);
                h1[s] = fmaf(__expf(dt1*a1), h1[s], u1*Bv[s]);
                yy0 = fmaf(h0[s], Cv[s], yy0);
                yy1 = fmaf(h1[s], Cv[s], yy1);
            }
            y0 = yy0; y1 = yy1;
        }

        Y0[t*NN] = fmaf(Dsk0, sc0, y0) * zg0;
        Y1[t*NN] = fmaf(Dsk1, sc1, y1) * zg1;

        __syncthreads();
        if (t + 2 < LF) kb_stage(base + (t+2)*NN, sbuf[t & 1], tid);
    }
}

// ========== Kernel C: folded out_proj∘blk + partial time-pooling ==========
__global__ void __launch_bounds__(256) kC(
    const float* __restrict__ out_w, const float* __restrict__ blk_w,
    const float* __restrict__ blk_b)
{
    const int id = blockIdx.x*256 + threadIdx.x;
    const int n = id & 511, chunk = (id >> 9) & 15, c = id >> 13;
    const int tid = threadIdx.x;

    __shared__ float s_M[8][16];
    __shared__ float s_bb[8];
    if (tid < 128) {
        int d = tid >> 4, i = tid & 15;
        float m = 0.f;
        #pragma unroll
        for (int e = 0; e < 8; ++e)
            m = fmaf(blk_w[(c*8+d)*8+e], out_w[(c*8+e)*16+i], m);
        s_M[d][i] = m;
        if (i == 0) s_bb[d] = blk_b[c*8+d];
    }
    __syncthreads();

    float acc[8] = {0,0,0,0,0,0,0,0};
    #pragma unroll 2
    for (int tt = 0; tt < 16; ++tt) {
        const int ctn = (c*LF + chunk*16 + tt)*NN + n;
        float y[16];
        #pragma unroll
        for (int di = 0; di < 16; ++di) y[di] = __ldg(&g_yf[di*PL + ctn]);
        #pragma unroll
        for (int d = 0; d < 8; ++d) {
            float v = s_bb[d];
            #pragma unroll
            for (int i = 0; i < 16; ++i) v = fmaf(y[i], s_M[d][i], v);
            acc[d] += fsilu(v);
        }
    }
    #pragma unroll
    for (int d = 0; d < 8; ++d)
        g_part[((c*16 + chunk)*NN + n)*8 + d] = acc[d];
}

// ========== Kernel D: final pooling + LayerNorm(64) ==========
__global__ void __launch_bounds__(64) kD(
    const float* __restrict__ ln_g, const float* __restrict__ ln_b,
    float* __restrict__ out)
{
    const int n = blockIdx.x, f = threadIdx.x;
    const int c = f >> 3, d = f & 7;
    float s = 0.f;
    #pragma unroll
    for (int ch = 0; ch < 16; ++ch)
        s += g_part[((c*16 + ch)*NN + n)*8 + d];
    float feat = s * (1.0f/256.0f);

    __shared__ float buf[64];
    buf[f] = feat;
    __syncthreads();
    float s1 = 0.f, s2 = 0.f;
    #pragma unroll
    for (int i = 0; i < 64; ++i) { float v = buf[i]; s1 += v; s2 = fmaf(v, v, s2); }
    float mu  = s1 * (1.0f/64.0f);
    float var = fmaxf(s2 * (1.0f/64.0f) - mu*mu, 0.f);
    float inv = rsqrtf(var + 1e-5f);
    out[n*64 + f] = (feat - mu) * inv * ln_g[f] + ln_b[f];
}

extern "C" void kernel_launch(void* const* d_in, const int* in_sizes, int n_in,
                              void* d_out, int out_size) {
    const float* x      = (const float*)d_in[0];
    const float* lift_w = (const float*)d_in[1];
    const float* lift_b = (const float*)d_in[2];
    const float* ipw    = (const float*)d_in[3];
    const float* conv_w = (const float*)d_in[4];
    const float* conv_b = (const float*)d_in[5];
    const float* xpw    = (const float*)d_in[6];
    const float* dt_w   = (const float*)d_in[7];
    const float* dt_b   = (const float*)d_in[8];
    const float* A_log  = (const float*)d_in[9];
    const float* D_skip = (const float*)d_in[10];
    const float* out_w  = (const float*)d_in[11];
    const float* blk_w  = (const float*)d_in[12];
    const float* blk_b  = (const float*)d_in[13];
    const float* ln_g   = (const float*)d_in[14];
    const float* ln_b   = (const float*)d_in[15];
    float* out = (float*)d_out;

    kA<<<dim3(LF, NC), 256>>>(x, lift_w, lift_b, ipw, conv_w, conv_b, xpw);
    kB<<<128, 256>>>(A_log, D_skip, dt_w, dt_b, lift_w, lift_b, ipw);
    kC<<<256, 256>>>(out_w, blk_w, blk_b);
    kD<<<NN, 64>>>(ln_g, ln_b, out);
}